// round 1
// baseline (speedup 1.0000x reference)
#include <cuda_runtime.h>
#include <math.h>

#define N 8192
#define D 64
#define THREADS 128
#define ROWS_PER_BLOCK 128
#define JSPLITS 4
#define JRANGE (N / JSPLITS)   // 2048
#define TILE_J 128
#define KNN 16

__device__ float g_norms[N];
__device__ float g_scratch[N * JSPLITS * KNN];  // partial top-16 d^2 per (row, split)
__device__ float g_mean[N];

__global__ void norms_kernel(const float* __restrict__ x) {
    int i = blockIdx.x * blockDim.x + threadIdx.x;
    if (i >= N) return;
    const float4* p = (const float4*)(x + (size_t)i * D);
    float s = 0.f;
#pragma unroll
    for (int q = 0; q < D / 4; q++) {
        float4 v = p[q];
        s += v.x * v.x + v.y * v.y + v.z * v.z + v.w * v.w;
    }
    g_norms[i] = s;
}

__global__ void __launch_bounds__(THREADS) knn_kernel(const float* __restrict__ x) {
    __shared__ float sj[TILE_J][D];   // 32 KB tile of candidate points
    __shared__ float sn[TILE_J];      // their norms

    const int rowBlock = blockIdx.x;          // 0..63
    const int split    = blockIdx.y;          // 0..JSPLITS-1
    const int i        = rowBlock * ROWS_PER_BLOCK + threadIdx.x;

    // query point in registers
    float xi[D];
#pragma unroll
    for (int q = 0; q < D / 4; q++) {
        float4 v = ((const float4*)(x + (size_t)i * D))[q];
        xi[4 * q + 0] = v.x; xi[4 * q + 1] = v.y;
        xi[4 * q + 2] = v.z; xi[4 * q + 3] = v.w;
    }
    const float x2i = g_norms[i];

    float t[KNN];
#pragma unroll
    for (int q = 0; q < KNN; q++) t[q] = 3.4e38f;
    float thr = 3.4e38f;

    const int j0 = split * JRANGE;

    for (int tile = 0; tile < JRANGE; tile += TILE_J) {
        __syncthreads();
        // cooperative coalesced load of TILE_J points
        {
            const float4* src = (const float4*)(x + (size_t)(j0 + tile) * D);
            float4* dst = (float4*)(&sj[0][0]);
            for (int q = threadIdx.x; q < TILE_J * D / 4; q += THREADS) dst[q] = src[q];
            if (threadIdx.x < TILE_J) sn[threadIdx.x] = g_norms[j0 + tile + threadIdx.x];
        }
        __syncthreads();

#pragma unroll 1
        for (int jj = 0; jj < TILE_J; jj++) {
            const float4* row = (const float4*)(&sj[jj][0]);
            float a0 = 0.f, a1 = 0.f, a2 = 0.f, a3 = 0.f;
#pragma unroll
            for (int q = 0; q < D / 4; q++) {
                float4 v = row[q];
                a0 = fmaf(xi[4 * q + 0], v.x, a0);
                a1 = fmaf(xi[4 * q + 1], v.y, a1);
                a2 = fmaf(xi[4 * q + 2], v.z, a2);
                a3 = fmaf(xi[4 * q + 3], v.w, a3);
            }
            float d2 = x2i + sn[jj] - 2.f * ((a0 + a1) + (a2 + a3));
            int jg = j0 + tile + jj;
            if (jg != i && d2 < thr) {
                // replace current max element, then refresh threshold
                float m = t[0]; int mi = 0;
#pragma unroll
                for (int q = 1; q < KNN; q++) { if (t[q] > m) { m = t[q]; mi = q; } }
#pragma unroll
                for (int q = 0; q < KNN; q++) { if (q == mi) t[q] = d2; }
                float nm = t[0];
#pragma unroll
                for (int q = 1; q < KNN; q++) nm = fmaxf(nm, t[q]);
                thr = nm;
            }
        }
    }

    float* out = g_scratch + ((size_t)i * JSPLITS + split) * KNN;
#pragma unroll
    for (int q = 0; q < KNN; q++) out[q] = t[q];
}

__global__ void merge_kernel() {
    int i = blockIdx.x * blockDim.x + threadIdx.x;
    if (i >= N) return;
    const float* c = g_scratch + (size_t)i * (JSPLITS * KNN);

    float t[KNN];
#pragma unroll
    for (int q = 0; q < KNN; q++) t[q] = 3.4e38f;
    float thr = 3.4e38f;

    for (int j = 0; j < JSPLITS * KNN; j++) {
        float d2 = c[j];
        if (d2 < thr) {
            float m = t[0]; int mi = 0;
#pragma unroll
            for (int q = 1; q < KNN; q++) { if (t[q] > m) { m = t[q]; mi = q; } }
#pragma unroll
            for (int q = 0; q < KNN; q++) { if (q == mi) t[q] = d2; }
            float nm = t[0];
#pragma unroll
            for (int q = 1; q < KNN; q++) nm = fmaxf(nm, t[q]);
            thr = nm;
        }
    }

    float s = 0.f;
#pragma unroll
    for (int q = 0; q < KNN; q++) s += (t[q] > 0.f) ? sqrtf(t[q]) : 0.f;
    g_mean[i] = s * (1.f / (float)KNN);
}

__global__ void loss_kernel(float* __restrict__ out) {
    __shared__ float s1[1024];
    __shared__ float s2[1024];
    int tid = threadIdx.x;

    float mx = -3.4e38f;
    for (int i = tid; i < N; i += 1024) mx = fmaxf(mx, g_mean[i]);
    s1[tid] = mx;
    __syncthreads();
    for (int o = 512; o > 0; o >>= 1) {
        if (tid < o) s1[tid] = fmaxf(s1[tid], s1[tid + o]);
        __syncthreads();
    }
    mx = s1[0];
    __syncthreads();

    float se = 0.f, sm = 0.f;
    for (int i = tid; i < N; i += 1024) {
        float v = g_mean[i];
        se += expf(v - mx);
        sm += v;
    }
    s1[tid] = se;
    s2[tid] = sm;
    __syncthreads();
    for (int o = 512; o > 0; o >>= 1) {
        if (tid < o) { s1[tid] += s1[tid + o]; s2[tid] += s2[tid + o]; }
        __syncthreads();
    }
    if (tid == 0) {
        float lse  = mx + logf(s1[0]);
        float mean = s2[0] / (float)N;
        out[0] = lse - mean - logf((float)N);
    }
}

extern "C" void kernel_launch(void* const* d_in, const int* in_sizes, int n_in,
                              void* d_out, int out_size) {
    const float* x = (const float*)d_in[0];
    (void)in_sizes; (void)n_in; (void)out_size;

    norms_kernel<<<N / 128, 128>>>(x);
    dim3 grid(N / ROWS_PER_BLOCK, JSPLITS);
    knn_kernel<<<grid, THREADS>>>(x);
    merge_kernel<<<N / 128, 128>>>();
    loss_kernel<<<1, 1024>>>((float*)d_out);
}